// round 11
// baseline (speedup 1.0000x reference)
#include <cuda_runtime.h>
#include <cstdint>

// Problem constants (fixed by the dataset)
#define BB 32
#define TT 2048
#define DD 256
#define D4 (DD / 4)              // 64 float4 lanes per row
#define MAX_SPAN 16
#define RBIN 64                  // t-rows per bin
#define NTBIN (TT / RBIN)        // 32 t-bins
#define NBIN (BB * NTBIN)        // 1024 bins
#define PROWS (RBIN + MAX_SPAN)  // 80 rows loaded per bin
#define MAIN_THREADS 512
#define SMEM_MAIN ((PROWS + 1) * DD * sizeof(float))   // 81 KB

// Binning scratch (CSR over span-sides). All reset per replay by k_zero /
// k_offsets, which run first in stream order.
__device__ int  g_bincnt[NBIN];
__device__ int  g_binstart[NBIN + 1];
__device__ int  g_bincur[NBIN];
__device__ int2 g_binlist[2 * 131072];   // 2*P entries (P<=131072), packed

// ---------------------------------------------------------------------------
// k_zero: reset bin counters (must precede k_count's atomics each replay).
// ---------------------------------------------------------------------------
__global__ void k_zero() {
    g_bincnt[threadIdx.x] = 0;
}

// ---------------------------------------------------------------------------
// k_count: one thread per pair; two atomicAdds (side1, side2 bins).
// ---------------------------------------------------------------------------
__global__ void k_count(const int* __restrict__ p1_start,
                        const int* __restrict__ p2_start,
                        const int* __restrict__ pair_batch,
                        int P) {
    const int p = blockIdx.x * blockDim.x + threadIdx.x;
    if (p >= P) return;
    const int b = pair_batch[p];
    atomicAdd(&g_bincnt[b * NTBIN + (p1_start[p] >> 6)], 1);
    atomicAdd(&g_bincnt[b * NTBIN + (p2_start[p] >> 6)], 1);
}

// ---------------------------------------------------------------------------
// k_offsets: single block, 1024 threads. Hillis-Steele inclusive scan ->
// exclusive bin starts + scatter cursors.
// ---------------------------------------------------------------------------
__global__ void k_offsets() {
    __shared__ int s[NBIN];
    const int t = threadIdx.x;
    const int cnt = g_bincnt[t];
    s[t] = cnt;
    __syncthreads();
    for (int off = 1; off < NBIN; off <<= 1) {
        int v = (t >= off) ? s[t - off] : 0;
        __syncthreads();
        s[t] += v;
        __syncthreads();
    }
    const int excl = s[t] - cnt;
    g_binstart[t] = excl;
    g_bincur[t]   = excl;
    if (t == NBIN - 1) g_binstart[NBIN] = s[t];
}

// ---------------------------------------------------------------------------
// k_scatter: one thread per pair; pack (pair*2+side, start|span<<16) into the
// bin lists. Order within a bin is nondeterministic but output-irrelevant
// (each entry owns a distinct output row).
// ---------------------------------------------------------------------------
__global__ void k_scatter(const int* __restrict__ p1_start,
                          const int* __restrict__ p1_span,
                          const int* __restrict__ p2_start,
                          const int* __restrict__ p2_span,
                          const int* __restrict__ pair_batch,
                          int P) {
    const int p = blockIdx.x * blockDim.x + threadIdx.x;
    if (p >= P) return;
    const int b  = pair_batch[p];
    const int s1 = p1_start[p], n1 = p1_span[p];
    const int s2 = p2_start[p], n2 = p2_span[p];

    int slot1 = atomicAdd(&g_bincur[b * NTBIN + (s1 >> 6)], 1);
    g_binlist[slot1] = make_int2(p * 2 + 0, s1 | (n1 << 16));
    int slot2 = atomicAdd(&g_bincur[b * NTBIN + (s2 >> 6)], 1);
    g_binlist[slot2] = make_int2(p * 2 + 1, s2 | (n2 << 16));
}

// ---------------------------------------------------------------------------
// k_main: one block per bin. Loads its (up to) 80 input rows into SMEM,
// builds a LOCAL exclusive prefix in place, then serves all spans in the bin
// from SMEM: 2 SMEM row-reads + 1 streaming DRAM row-write per span.
// 512 threads = 8 groups of 64; each group processes spans strided by 8,
// with next-entry prefetch to hide the L2 entry-load latency.
// ---------------------------------------------------------------------------
__global__ __launch_bounds__(MAIN_THREADS, 2)
void k_main(const float* __restrict__ x, float* __restrict__ out) {
    extern __shared__ float ps[];    // (PROWS+1) x DD floats

    const int bin = blockIdx.x;
    const int b   = bin >> 5;            // bin / NTBIN
    const int t0  = (bin & (NTBIN - 1)) * RBIN;
    const int rows = (TT - t0 < PROWS) ? (TT - t0) : PROWS;

    // ---- Phase 1: coalesced load of rows [t0, t0+rows) into SMEM
    {
        const float4* g = reinterpret_cast<const float4*>(x)
                          + ((size_t)b * TT + t0) * D4;
        float4* s4 = reinterpret_cast<float4*>(ps);
        const int nv = rows * D4;
        for (int j = threadIdx.x; j < nv; j += MAIN_THREADS)
            s4[j] = __ldcs(&g[j]);
    }
    __syncthreads();

    // ---- Phase 2: in-place exclusive column prefix (thread = column d).
    //      8-wide register prefetch breaks the serial load chain.
    if (threadIdx.x < DD) {
        const int d = threadIdx.x;
        float acc = 0.0f;
        int t = 0;
        for (; t + 8 <= rows; t += 8) {
            float v[8];
#pragma unroll
            for (int i = 0; i < 8; i++) v[i] = ps[(t + i) * DD + d];
#pragma unroll
            for (int i = 0; i < 8; i++) {
                ps[(t + i) * DD + d] = acc;
                acc += v[i];
            }
        }
        for (; t < rows; t++) {
            float v = ps[t * DD + d];
            ps[t * DD + d] = acc;
            acc += v;
        }
        ps[rows * DD + d] = acc;
    }
    __syncthreads();

    // ---- Phase 3: serve spans. group = 64 threads, one float4 lane each.
    const int e0 = g_binstart[bin];
    const int e1 = g_binstart[bin + 1];
    const int grp = threadIdx.x >> 6;    // 0..7
    const int ln  = threadIdx.x & 63;

    const float4* s4 = reinterpret_cast<const float4*>(ps);
    float4* o4 = reinterpret_cast<float4*>(out);

    int e = e0 + grp;
    if (e >= e1) return;
    int2 ent = g_binlist[e];
    for (; e < e1; e += 8) {
        int2 nxt;
        if (e + 8 < e1) nxt = g_binlist[e + 8];   // prefetch next entry

        const int rowid = ent.x;                   // pair*2 + side
        const int a = (ent.y & 0xFFFF) - t0;       // local start
        const int n = ent.y >> 16;                 // span

        float4 lo = s4[a * D4 + ln];
        float4 hi = s4[(a + n) * D4 + ln];
        const float inv = 1.0f / (float)n;

        float4 r;
        r.x = (hi.x - lo.x) * inv;
        r.y = (hi.y - lo.y) * inv;
        r.z = (hi.z - lo.z) * inv;
        r.w = (hi.w - lo.w) * inv;
        __stcs(&o4[(size_t)rowid * D4 + ln], r);

        ent = nxt;
    }
}

// ---------------------------------------------------------------------------
extern "C" void kernel_launch(void* const* d_in, const int* in_sizes, int n_in,
                              void* d_out, int out_size) {
    const float* token_embs = (const float*)d_in[0];
    const int* p1_start   = (const int*)d_in[1];
    const int* p1_span    = (const int*)d_in[2];
    const int* p2_start   = (const int*)d_in[3];
    const int* p2_span    = (const int*)d_in[4];
    const int* pair_batch = (const int*)d_in[5];
    float* out = (float*)d_out;

    const int P = in_sizes[1];
    const int gP = (P + 255) / 256;

    static bool attr_done = false;
    if (!attr_done) {
        cudaFuncSetAttribute(k_main, cudaFuncAttributeMaxDynamicSharedMemorySize,
                             (int)SMEM_MAIN);
        attr_done = true;
    }

    k_zero<<<1, NBIN>>>();
    k_count<<<gP, 256>>>(p1_start, p2_start, pair_batch, P);
    k_offsets<<<1, NBIN>>>();
    k_scatter<<<gP, 256>>>(p1_start, p1_span, p2_start, p2_span, pair_batch, P);
    k_main<<<NBIN, MAIN_THREADS, SMEM_MAIN>>>(token_embs, out);
}

// round 15
// speedup vs baseline: 1.0270x; 1.0270x over previous
#include <cuda_runtime.h>
#include <cstdint>

// Problem constants (fixed by the dataset)
#define BB 32
#define TT 2048
#define DD 256
#define D4 (DD / 4)              // 64 float4 lanes per row
#define MAX_SPAN 16
#define RBIN 64                  // t-rows per bin
#define NTBIN (TT / RBIN)        // 32 t-bins
#define NBIN (BB * NTBIN)        // 1024 bins
#define PROWS (RBIN + MAX_SPAN)  // 80 rows loaded per bin
#define CAP 512                  // slots per bin (expected ~195, >20 sigma)
#define MAIN_THREADS 512
#define SMEM_MAIN ((PROWS + 1) * DD * sizeof(float))   // 81 KB

// Binning scratch. g_bincnt starts zeroed (static init) and is re-zeroed by
// k_main each run (stream order: scatter -> main -> next replay's scatter).
__device__ int  g_bincnt[NBIN];
__device__ int2 g_binlist[NBIN * CAP];   // 4 MB

// ---------------------------------------------------------------------------
// k_scatter: ONE thread per span-side (2P threads). Segmented so loads stay
// coalesced: threads [0,P) handle side 1, [P,2P) handle side 2.
// Single atomicAdd + one 8-byte store per thread.
// ---------------------------------------------------------------------------
__global__ __launch_bounds__(256)
void k_scatter(const int* __restrict__ p1_start,
               const int* __restrict__ p1_span,
               const int* __restrict__ p2_start,
               const int* __restrict__ p2_span,
               const int* __restrict__ pair_batch,
               int P) {
    const int i = blockIdx.x * 256 + threadIdx.x;
    if (i >= 2 * P) return;

    int p, start, span, row;
    if (i < P) {
        p = i;
        start = p1_start[p];
        span  = p1_span[p];
        row   = 2 * p;
    } else {
        p = i - P;
        start = p2_start[p];
        span  = p2_span[p];
        row   = 2 * p + 1;
    }
    const int b   = pair_batch[p];
    const int bin = b * NTBIN + (start >> 6);

    const int slot = atomicAdd(&g_bincnt[bin], 1);
    if (slot < CAP) {
        g_binlist[bin * CAP + slot] = make_int2(row, start | (span << 16));
    }
}

// ---------------------------------------------------------------------------
// k_main: one block per bin. Loads its (up to) 80 input rows into SMEM,
// builds a LOCAL exclusive prefix in place, then serves all spans in the bin
// from SMEM: 2 SMEM row-reads + 1 streaming DRAM row-write per span.
// 512 threads = 8 groups of 64; groups process spans strided by 8 with
// next-entry prefetch. Thread 0 resets the bin counter for the next replay.
// ---------------------------------------------------------------------------
__global__ __launch_bounds__(MAIN_THREADS, 2)
void k_main(const float* __restrict__ x, float* __restrict__ out) {
    extern __shared__ float ps[];    // (PROWS+1) x DD floats
    __shared__ int s_cnt;

    const int bin = blockIdx.x;
    const int b   = bin >> 5;            // bin / NTBIN
    const int t0  = (bin & (NTBIN - 1)) * RBIN;
    const int rows = (TT - t0 < PROWS) ? (TT - t0) : PROWS;

    if (threadIdx.x == 0) {
        int c = g_bincnt[bin];
        s_cnt = (c < CAP) ? c : CAP;
        g_bincnt[bin] = 0;               // reset for next graph replay
    }

    // ---- Phase 1: coalesced load of rows [t0, t0+rows) into SMEM
    {
        const float4* g = reinterpret_cast<const float4*>(x)
                          + ((size_t)b * TT + t0) * D4;
        float4* s4 = reinterpret_cast<float4*>(ps);
        const int nv = rows * D4;
        for (int j = threadIdx.x; j < nv; j += MAIN_THREADS)
            s4[j] = __ldcs(&g[j]);
    }
    __syncthreads();

    // ---- Phase 2: in-place exclusive column prefix (thread = column d).
    //      8-wide register prefetch breaks the serial load chain.
    if (threadIdx.x < DD) {
        const int d = threadIdx.x;
        float acc = 0.0f;
        int t = 0;
        for (; t + 8 <= rows; t += 8) {
            float v[8];
#pragma unroll
            for (int i = 0; i < 8; i++) v[i] = ps[(t + i) * DD + d];
#pragma unroll
            for (int i = 0; i < 8; i++) {
                ps[(t + i) * DD + d] = acc;
                acc += v[i];
            }
        }
        for (; t < rows; t++) {
            float v = ps[t * DD + d];
            ps[t * DD + d] = acc;
            acc += v;
        }
        ps[rows * DD + d] = acc;
    }
    __syncthreads();

    // ---- Phase 3: serve spans. group = 64 threads, one float4 lane each.
    const int cnt = s_cnt;
    const int e0  = bin * CAP;
    const int e1  = e0 + cnt;
    const int grp = threadIdx.x >> 6;    // 0..7
    const int ln  = threadIdx.x & 63;

    const float4* s4 = reinterpret_cast<const float4*>(ps);
    float4* o4 = reinterpret_cast<float4*>(out);

    int e = e0 + grp;
    if (e >= e1) return;
    int2 ent = g_binlist[e];
    for (; e < e1; e += 8) {
        int2 nxt;
        if (e + 8 < e1) nxt = g_binlist[e + 8];   // prefetch next entry

        const int rowid = ent.x;                   // pair*2 + side
        const int a = (ent.y & 0xFFFF) - t0;       // local start
        const int n = ent.y >> 16;                 // span

        float4 lo = s4[a * D4 + ln];
        float4 hi = s4[(a + n) * D4 + ln];
        const float inv = 1.0f / (float)n;

        float4 r;
        r.x = (hi.x - lo.x) * inv;
        r.y = (hi.y - lo.y) * inv;
        r.z = (hi.z - lo.z) * inv;
        r.w = (hi.w - lo.w) * inv;
        __stcs(&o4[(size_t)rowid * D4 + ln], r);

        ent = nxt;
    }
}

// ---------------------------------------------------------------------------
extern "C" void kernel_launch(void* const* d_in, const int* in_sizes, int n_in,
                              void* d_out, int out_size) {
    const float* token_embs = (const float*)d_in[0];
    const int* p1_start   = (const int*)d_in[1];
    const int* p1_span    = (const int*)d_in[2];
    const int* p2_start   = (const int*)d_in[3];
    const int* p2_span    = (const int*)d_in[4];
    const int* pair_batch = (const int*)d_in[5];
    float* out = (float*)d_out;

    const int P = in_sizes[1];

    static bool attr_done = false;
    if (!attr_done) {
        cudaFuncSetAttribute(k_main, cudaFuncAttributeMaxDynamicSharedMemorySize,
                             (int)SMEM_MAIN);
        attr_done = true;
    }

    const int gS = (2 * P + 255) / 256;
    k_scatter<<<gS, 256>>>(p1_start, p1_span, p2_start, p2_span, pair_batch, P);
    k_main<<<NBIN, MAIN_THREADS, SMEM_MAIN>>>(token_embs, out);
}